// round 16
// baseline (speedup 1.0000x reference)
#include <cuda_runtime.h>
#include <cuda_fp16.h>
#include <cstdint>

typedef unsigned long long ull;

#define BROWS 8192
#define NOUT  512
#define NKDIM 512
#define NCODE 512
#define GROUPS 4096
#define WDIM   64

#define KEFF  1024          // 2 fp16 precision segments * 512
#define GBM   128
#define GBN   128
#define GBK   32
#define KITERS (KEFF / GBK) // 32
#define ASTR  40            // padded f16 row stride (conflict-free ldmatrix)
#define NSTAGE 3
#define SMEM_BYTES (NSTAGE * (GBM + GBN) * ASTR * 2)   // 61440

// ---------------- device scratch ----------------
__device__ __half g_A2[BROWS * KEFF];   // 16.8 MB  [Ah | Al]
__device__ __half g_B2[NOUT * KEFF];    // 1.0 MB   [Bh | Bh]
__device__ int   g_idx[GROUPS];
__device__ float g_mind[GROUPS];

__device__ __forceinline__ uint32_t smem_u32(const void* p) {
    uint32_t a;
    asm("{ .reg .u64 t; cvta.to.shared.u64 t, %1; cvt.u32.u64 %0, t; }" : "=r"(a) : "l"(p));
    return a;
}
__device__ __forceinline__ void cp16(uint32_t dst, const void* src) {
    asm volatile("cp.async.cg.shared.global [%0], [%1], 16;" :: "r"(dst), "l"(src));
}
#define CP_COMMIT() asm volatile("cp.async.commit_group;" ::: "memory")
#define CP_WAIT0()  asm volatile("cp.async.wait_group 0;" ::: "memory")
#define CP_WAIT1()  asm volatile("cp.async.wait_group 1;" ::: "memory")

__device__ __forceinline__ void ldm_x4(uint32_t addr, uint32_t& r0, uint32_t& r1,
                                       uint32_t& r2, uint32_t& r3) {
    asm volatile("ldmatrix.sync.aligned.m8n8.x4.shared.b16 {%0,%1,%2,%3}, [%4];"
                 : "=r"(r0), "=r"(r1), "=r"(r2), "=r"(r3) : "r"(addr));
}
__device__ __forceinline__ void mma_f16(float* d, const uint32_t* a, const uint32_t* b) {
    asm volatile(
        "mma.sync.aligned.m16n8k16.row.col.f32.f16.f16.f32 "
        "{%0,%1,%2,%3}, {%4,%5,%6,%7}, {%8,%9}, {%0,%1,%2,%3};"
        : "+f"(d[0]), "+f"(d[1]), "+f"(d[2]), "+f"(d[3])
        : "r"(a[0]), "r"(a[1]), "r"(a[2]), "r"(a[3]), "r"(b[0]), "r"(b[1]));
}

// =====================================================================
// Kernel 1: VQ quantize. Same math/row-mapping as verified R14;
// ONLY change: inner loop reads w_s via float4 (LDS.128 broadcast) and
// unrolls k by 4 — 4x fewer shared-memory instructions.
// =====================================================================
#define VQ_ROWS 8

__global__ __launch_bounds__(512) void vq_kernel(
    const float* __restrict__ weight, const float* __restrict__ embed)
{
    __shared__ __align__(16) float w_s[VQ_ROWS][WDIM];
    __shared__ float wn_s[VQ_ROWS];
    __shared__ float dist_s[VQ_ROWS][NCODE];

    const int tid = threadIdx.x;
    const int r0  = blockIdx.x * VQ_ROWS;

    for (int t = tid; t < VQ_ROWS * WDIM; t += 512)
        w_s[t / WDIM][t % WDIM] = weight[r0 * WDIM + t];
    __syncthreads();

    if (tid < VQ_ROWS) {
        float s = 0.f;
#pragma unroll
        for (int k = 0; k < WDIM; k++) { float v = w_s[tid][k]; s += v * v; }
        wn_s[tid] = s;
    }

    float acc[VQ_ROWS];
#pragma unroll
    for (int r = 0; r < VQ_ROWS; r++) acc[r] = 0.f;
    float en = 0.f;
    const int j = tid;
#pragma unroll
    for (int k4 = 0; k4 < WDIM / 4; k4++) {
        const int k = k4 * 4;
        const float e0 = embed[(k + 0) * NCODE + j];
        const float e1 = embed[(k + 1) * NCODE + j];
        const float e2 = embed[(k + 2) * NCODE + j];
        const float e3 = embed[(k + 3) * NCODE + j];
        en += e0 * e0; en += e1 * e1; en += e2 * e2; en += e3 * e3;
#pragma unroll
        for (int r = 0; r < VQ_ROWS; r++) {
            const float4 w4 = *(const float4*)&w_s[r][k];
            acc[r] += w4.x * e0;
            acc[r] += w4.y * e1;
            acc[r] += w4.z * e2;
            acc[r] += w4.w * e3;
        }
    }
#pragma unroll
    for (int r = 0; r < VQ_ROWS; r++) dist_s[r][j] = en - 2.f * acc[r];
    __syncthreads();

    const int warp = tid >> 5, lane = tid & 31;
    if (warp < VQ_ROWS) {
        float best = 3.4e38f; int bi = 0;
        for (int c = lane; c < NCODE; c += 32) {
            float v = dist_s[warp][c];
            if (v < best) { best = v; bi = c; }
        }
#pragma unroll
        for (int off = 16; off > 0; off >>= 1) {
            float ov = __shfl_down_sync(0xffffffffu, best, off);
            int   oi = __shfl_down_sync(0xffffffffu, bi,   off);
            if (ov < best) { best = ov; bi = oi; }
        }
        if (lane == 0) {
            g_idx[r0 + warp]  = bi;
            g_mind[r0 + warp] = wn_s[warp] + best;
        }
    }
}

// =====================================================================
// Kernel 2: MERGED converts (verified R13/R14). Blocks 0..511: B2 +
// diff fold. Blocks 512..8703: A2 convert.
// =====================================================================
#define CB_BLOCKS NOUT          // 512
#define MERGED_BLOCKS (CB_BLOCKS + BROWS)

__global__ __launch_bounds__(256) void convert_ab(
    const float* __restrict__ x,
    const float* __restrict__ embed, const float* __restrict__ weight,
    const int* __restrict__ use_qw_p, float* __restrict__ out, int out_size)
{
    if (blockIdx.x >= CB_BLOCKS) {
        const int m = blockIdx.x - CB_BLOCKS;
        const int k = threadIdx.x * 2;

        const float2 v = *(const float2*)&x[m * NKDIM + k];
        __half2 hi = __float22half2_rn(v);
        float2 hf = __half22float2(hi);
        __half2 lo = __float22half2_rn(make_float2(v.x - hf.x, v.y - hf.y));

        __half* row = g_A2 + (size_t)m * KEFF;
        *(__half2*)&row[k]       = hi;
        *(__half2*)&row[512 + k] = lo;
        return;
    }

    const int n = blockIdx.x;          // 0..511
    const int k = threadIdx.x * 2;     // even k
    const int g = k >> 3, i0 = k & 7;
    const int og = n >> 3, om = n & 7;
    const int uq = use_qw_p ? *use_qw_p : 1;

    float v0, v1;
    if (uq) {
        const int ix = g_idx[g * 64 + og];
        v0 = embed[(i0 * 8 + om) * NCODE + ix];
        v1 = embed[((i0 + 1) * 8 + om) * NCODE + ix];
    } else {
        v0 = weight[(g * 64 + og) * WDIM + i0 * 8 + om];
        v1 = weight[(g * 64 + og) * WDIM + (i0 + 1) * 8 + om];
    }
    __half2 hi = __float22half2_rn(make_float2(v0, v1));

    __half* row = g_B2 + (size_t)n * KEFF;
    *(__half2*)&row[k]       = hi;
    *(__half2*)&row[512 + k] = hi;

    if (blockIdx.x == 0) {
        __shared__ float s[256];
        float a = 0.f;
        for (int i = threadIdx.x; i < GROUPS; i += 256) a += g_mind[i];
        s[threadIdx.x] = a;
        __syncthreads();
        for (int st = 128; st > 0; st >>= 1) {
            if (threadIdx.x < st) s[threadIdx.x] += s[threadIdx.x + st];
            __syncthreads();
        }
        if (threadIdx.x == 0 && out_size > BROWS * NOUT)
            out[BROWS * NOUT] = uq ? (s[0] / (float)(GROUPS * WDIM)) : 0.f;
    }
}

// =====================================================================
// Kernel 3: fp16 mma.sync GEMM, 3-stage pipeline (verified R13/R14).
// =====================================================================
__global__ __launch_bounds__(256, 2) void gemm_mma(float* __restrict__ C)
{
    extern __shared__ __half sh[];
    __half* const AsBase = sh;                        // [NSTAGE][GBM][ASTR]
    __half* const BsBase = sh + NSTAGE * GBM * ASTR;  // [NSTAGE][GBN][ASTR]

    const int tid  = threadIdx.x;
    const int lane = tid & 31;
    const int wid  = tid >> 5;
    const int wm   = wid & 3;
    const int wn   = wid >> 2;

    const int m0 = blockIdx.y * GBM;
    const int n0 = blockIdx.x * GBN;

    const __half* Ag = g_A2 + (size_t)m0 * KEFF;
    const __half* Bg = g_B2 + (size_t)n0 * KEFF;

    const int c0_row = tid >> 2;
    const int c0_seg = tid & 3;
    const int c1_row = (tid + 256) >> 2;
    const int c1_seg = tid & 3;

    float acc[2][8][4];
#pragma unroll
    for (int mt = 0; mt < 2; mt++)
#pragma unroll
        for (int nt = 0; nt < 8; nt++)
#pragma unroll
            for (int q = 0; q < 4; q++) acc[mt][nt][q] = 0.f;

    auto load_stage = [&](int s, int kt) {
        __half* As = AsBase + s * (GBM * ASTR);
        __half* Bs = BsBase + s * (GBN * ASTR);
        cp16(smem_u32(&As[c0_row * ASTR + c0_seg * 8]), Ag + (size_t)c0_row * KEFF + kt + c0_seg * 8);
        cp16(smem_u32(&As[c1_row * ASTR + c1_seg * 8]), Ag + (size_t)c1_row * KEFF + kt + c1_seg * 8);
        cp16(smem_u32(&Bs[c0_row * ASTR + c0_seg * 8]), Bg + (size_t)c0_row * KEFF + kt + c0_seg * 8);
        cp16(smem_u32(&Bs[c1_row * ASTR + c1_seg * 8]), Bg + (size_t)c1_row * KEFF + kt + c1_seg * 8);
    };

    load_stage(0, 0); CP_COMMIT();
    load_stage(1, GBK); CP_COMMIT();

    int s = 0;
    for (int it = 0; it < KITERS; it++) {
        if (it + 1 < KITERS) { CP_WAIT1(); } else { CP_WAIT0(); }
        __syncthreads();
        if (it + 2 < KITERS) {
            int sn = s + 2; if (sn >= NSTAGE) sn -= NSTAGE;
            load_stage(sn, (it + 2) * GBK);
            CP_COMMIT();
        }

        const __half* As = AsBase + s * (GBM * ASTR);
        const __half* Bs = BsBase + s * (GBN * ASTR);
        const uint32_t a_lane0 = smem_u32(As) +
            ((wm * 32 + (lane & 15)) * ASTR + (lane >> 4) * 8) * 2;
        const int bq = lane >> 3, br = lane & 7;
        const uint32_t b_lane0 = smem_u32(Bs) +
            ((wn * 64 + (bq >> 1) * 8 + br) * ASTR + (bq & 1) * 8) * 2;

#pragma unroll
        for (int ks = 0; ks < 2; ks++) {
            uint32_t a[2][4], b[8][2];
#pragma unroll
            for (int mt = 0; mt < 2; mt++)
                ldm_x4(a_lane0 + (mt * 16 * ASTR + ks * 16) * 2,
                       a[mt][0], a[mt][1], a[mt][2], a[mt][3]);
#pragma unroll
            for (int np = 0; np < 4; np++)
                ldm_x4(b_lane0 + (np * 16 * ASTR + ks * 16) * 2,
                       b[np * 2][0], b[np * 2][1], b[np * 2 + 1][0], b[np * 2 + 1][1]);
#pragma unroll
            for (int mt = 0; mt < 2; mt++)
#pragma unroll
                for (int nt = 0; nt < 8; nt++)
                    mma_f16(acc[mt][nt], a[mt], b[nt]);
        }

        if (++s >= NSTAGE) s = 0;
    }

    // Epilogue
#pragma unroll
    for (int mt = 0; mt < 2; mt++) {
        const int r0 = m0 + wm * 32 + mt * 16 + (lane >> 2);
#pragma unroll
        for (int nt = 0; nt < 8; nt++) {
            const int c = n0 + wn * 64 + nt * 8 + (lane & 3) * 2;
            *(float2*)&C[(size_t)r0 * NOUT + c]       = make_float2(acc[mt][nt][0], acc[mt][nt][1]);
            *(float2*)&C[(size_t)(r0 + 8) * NOUT + c] = make_float2(acc[mt][nt][2], acc[mt][nt][3]);
        }
    }
}

// =====================================================================
extern "C" void kernel_launch(void* const* d_in, const int* in_sizes, int n_in,
                              void* d_out, int out_size)
{
    const float* x      = (const float*)d_in[0];   // [8192, 512]
    const float* weight = (const float*)d_in[1];   // [64,64,8,8]
    const float* embed  = (const float*)d_in[2];   // [64,512]
    const int*   use_qw = (n_in >= 4) ? (const int*)d_in[3] : nullptr;
    float* out = (float*)d_out;

    cudaFuncSetAttribute(gemm_mma, cudaFuncAttributeMaxDynamicSharedMemorySize,
                         SMEM_BYTES);

    vq_kernel<<<GROUPS / VQ_ROWS, 512>>>(weight, embed);
    convert_ab<<<MERGED_BLOCKS, 256>>>(x, embed, weight, use_qw, out, out_size);
    gemm_mma<<<dim3(NOUT / GBN, BROWS / GBM), 256, SMEM_BYTES>>>(out);
}